// round 16
// baseline (speedup 1.0000x reference)
#include <cuda_runtime.h>

// Fixed shapes: B=2, H=8, S=256, d=64
#define NB 2
#define NH 8
#define NS 256
#define ND 64
#define PER_B (NH*NS*ND)      // 131072 floats per batch in Q/V
#define OUT_HALF (NB*PER_B)   // 262144 floats: attn offset (context first, attn second)

// W[b][u][e] = sum_{r=0..7} Q[b*131072 + u*512 + r*64 + e] * V[same], u in [0,256)
// g_CP[b][c][i][e] = inclusive prefix of W over i within chunk c (u = c*64+i).
__device__ float g_CP[NB][4][64][64];

// 24 (h,s7) combos whose windows are ALWAYS empty (v=2*s7+h outside [6,15]):
// those 1536 rows get uniform softmax: attn = 1/64, ctx = V/64.
__constant__ unsigned char c_light[24][2] = {
    {0,0},{1,0},{2,0},{0,1},{3,0},{1,1},{4,0},{2,1},{0,2},{5,0},{3,1},{1,2},
    {2,7},{4,6},{6,5},{3,7},{5,6},{7,5},{4,7},{6,6},{5,7},{7,6},{6,7},{7,7}
};

// Kernel 1: 32 blocks x 256 (blk = b*16 + c*4 + eq; eq = 16-wide e slice).
// Two-level prefix: shortens the serial chain from 64 adds to ~4+15+4 adds.
__global__ void __launch_bounds__(256) k_chunk_prefix(const float* __restrict__ Q,
                                                      const float* __restrict__ V) {
    int blk = blockIdx.x;
    int b  = blk >> 4;
    int c  = (blk >> 2) & 3;
    int eq = blk & 3;

    __shared__ float Wsm[64][16];
    __shared__ float Ssm[16][17];   // partial sums per (u-quarter, e-col), padded

    int tid = threadIdx.x;

    // ---- Phase A: W tile (identical to proven round-2 body) ----
    {
        int ul = tid >> 2;   // 0..63
        int e4 = tid & 3;    // float4 column within the 16-e slice

        const float4* Q4 = reinterpret_cast<const float4*>(Q) + b * (PER_B / 4);
        const float4* V4 = reinterpret_cast<const float4*>(V) + b * (PER_B / 4);

        int u = c * 64 + ul;
        int base4 = u * 128 + eq * 4 + e4;   // float4 index of (u*512 + eq*16 + e4*4)

        float4 acc = make_float4(0.f, 0.f, 0.f, 0.f);
        #pragma unroll
        for (int r = 0; r < 8; r++) {
            float4 q = Q4[base4 + r * 16];
            float4 v = V4[base4 + r * 16];
            acc.x = fmaf(q.x, v.x, acc.x);
            acc.y = fmaf(q.y, v.y, acc.y);
            acc.z = fmaf(q.z, v.z, acc.z);
            acc.w = fmaf(q.w, v.w, acc.w);
        }
        *reinterpret_cast<float4*>(&Wsm[ul][e4 * 4]) = acc;
    }
    __syncthreads();

    // ---- Phase B: two-level inclusive prefix along u ----
    // 16 threads per e-column; thread (q, e16) owns u-local [4q, 4q+4).
    int e16 = tid & 15;
    int q   = tid >> 4;      // 0..15
    int u0  = q * 4;

    float w0 = Wsm[u0 + 0][e16];
    float w1 = Wsm[u0 + 1][e16];
    float w2 = Wsm[u0 + 2][e16];
    float w3 = Wsm[u0 + 3][e16];
    Ssm[q][e16] = ((w0 + w1) + (w2 + w3));
    __syncthreads();

    float off = 0.f;
    #pragma unroll
    for (int j = 0; j < 15; j++)
        if (j < q) off += Ssm[j][e16];

    float r0 = off + w0;
    float r1 = r0 + w1;
    float r2 = r1 + w2;
    float r3 = r2 + w3;
    float* dst = &g_CP[b][c][u0][eq * 16 + e16];
    dst[0]   = r0;
    dst[64]  = r1;
    dst[128] = r2;
    dst[192] = r3;
}

// Kernel 2: 96 blocks x 512 threads (round-15 structure, measured 4.96us).
//   Blocks 0..79  : heavy rows, one per half-warp; CP loads issued FIRST
//                   (they are the dependent-critical chain), V load after.
//   Blocks 80..95 : uniform rows under the heavy umbrella.
__global__ void __launch_bounds__(512) k_stage2(const float* __restrict__ V,
                                                float* __restrict__ out) {
    int tid = threadIdx.x;
    int blk = blockIdx.x;

    const float4* V4g  = reinterpret_cast<const float4*>(V);
    float4*       out4 = reinterpret_cast<float4*>(out);

    if (blk >= 80) {
        // ---- Uniform rows: 24576 float4-slot tasks / 8192 workers = 3 passes ----
        const float uinv = 1.0f / 64.0f;
        int k0 = (blk - 80) * 512 + tid;
        #pragma unroll
        for (int it = 0; it < 3; it++) {
            int k = k0 + it * 8192;
            int r = k >> 4, l = k & 15;
            int bb = r >= 768;
            int rr = r - bb * 768;
            int pi = rr >> 5, s_hi = rr & 31;
            int h  = c_light[pi][0], s7 = c_light[pi][1];
            int grow = ((bb * 8 + h) << 8) + s_hi * 8 + s7;
            float4 vv = V4g[grow * 16 + l];
            out4[(OUT_HALF / 4) + grow * 16 + l] =
                make_float4(uinv, uinv, uinv, uinv);
            out4[grow * 16 + l] =
                make_float4(vv.x * uinv, vv.y * uinv, vv.z * uinv, vv.w * uinv);
        }
        return;
    }

    // ---- Heavy rows: 2560 rows, one per half-warp ----
    int hw = tid >> 4;          // half-warp id within block: 0..31
    int l  = tid & 15;          // e-slot: e = 4l..4l+3

    int rowid = blk * 32 + hw;             // 0..2559
    int b     = rowid >= 1280;
    int rem   = rowid - b * 1280;
    int vi    = rem >> 7;                  // 0..9
    int rem2  = rem & 127;
    int combo = rem2 >> 5;                 // 0..3
    int s_hi  = rem2 & 31;
    int v  = vi + 6;
    int s7 = ((v - 6) >> 1) + combo;
    int h  = v - 2 * s7;
    int grow = ((b * 8 + h) << 8) + s_hi * 8 + s7;
    int base = (((v << 5) + 256) & 511) + s_hi;   // base_row, <= 511

    const float4* CP4 = reinterpret_cast<const float4*>(g_CP);
    float4 sc = make_float4(0.f, 0.f, 0.f, 0.f);

    // CP loads first: they gate the softmax chain.
    if (base < 256) {
        int lo = base, hi = min(base + 63, 255);
        int c0 = lo >> 6, c1 = hi >> 6;
        int i0 = lo & 63, i1 = hi & 63;
        float4 hiV = CP4[((b * 4 + c1) * 64 + i1) * 16 + l];
        float4 loV = make_float4(0.f, 0.f, 0.f, 0.f);
        if (i0 > 0) loV = CP4[((b * 4 + c0) * 64 + (i0 - 1)) * 16 + l];
        if (c0 == c1) {
            sc = make_float4(hiV.x - loV.x, hiV.y - loV.y,
                             hiV.z - loV.z, hiV.w - loV.w);
        } else {
            float4 T = CP4[((b * 4 + c0) * 64 + 63) * 16 + l];
            sc = make_float4((T.x - loV.x) + hiV.x, (T.y - loV.y) + hiV.y,
                             (T.z - loV.z) + hiV.z, (T.w - loV.w) + hiV.w);
        }
    } else if (base > 448) {
        sc = CP4[((b * 4 + 0) * 64 + (base - 449)) * 16 + l];  // wrap: chunk 0
    }
    // else (v=6, s_hi=0): empty -> sc = 0 -> uniform softmax

    int off4 = grow * 16 + l;
    float4 vv = V4g[off4];      // independent of the softmax chain

    // softmax over 64 e's: 4 per lane, reduce across the 16-lane half-warp.
    float m = fmaxf(fmaxf(sc.x, sc.y), fmaxf(sc.z, sc.w));
    #pragma unroll
    for (int d_ = 8; d_ > 0; d_ >>= 1)
        m = fmaxf(m, __shfl_xor_sync(0xffffffffu, m, d_));

    float e0 = __expf(sc.x - m);
    float e1 = __expf(sc.y - m);
    float e2 = __expf(sc.z - m);
    float e3 = __expf(sc.w - m);
    float ssum = (e0 + e1) + (e2 + e3);
    #pragma unroll
    for (int d_ = 8; d_ > 0; d_ >>= 1)
        ssum += __shfl_xor_sync(0xffffffffu, ssum, d_);
    float inv = __frcp_rn(ssum);

    float4 a = make_float4(e0 * inv, e1 * inv, e2 * inv, e3 * inv);

    out4[(OUT_HALF / 4) + off4] = a;                                       // attn
    out4[off4] = make_float4(a.x * vv.x, a.y * vv.y, a.z * vv.z, a.w * vv.w); // context
}

extern "C" void kernel_launch(void* const* d_in, const int* in_sizes, int n_in,
                              void* d_out, int out_size) {
    const float* Q = (const float*)d_in[0];
    // d_in[1] (K) is genuinely unused by the reference computation.
    const float* V = (const float*)d_in[2];
    float* out = (float*)d_out;

    k_chunk_prefix<<<32, 256>>>(Q, V);
    k_stage2<<<96, 512>>>(V, out);
}

// round 17
// speedup vs baseline: 1.0564x; 1.0564x over previous
#include <cuda_runtime.h>

// Fixed shapes: B=2, H=8, S=256, d=64
#define NB 2
#define NH 8
#define NS 256
#define ND 64
#define PER_B (NH*NS*ND)      // 131072 floats per batch in Q/V
#define OUT_HALF (NB*PER_B)   // 262144 floats: attn offset (context first, attn second)

// W[b][u][e] = sum_{r=0..7} Q[b*131072 + u*512 + r*64 + e] * V[same], u in [0,256)
// g_CP[b][c][i][e] = inclusive prefix of W over i within chunk c (u = c*64+i).
__device__ float g_CP[NB][4][64][64];

// 24 (h,s7) combos whose windows are ALWAYS empty (v=2*s7+h outside [6,15]):
// those 1536 rows get uniform softmax: attn = 1/64, ctx = V/64.
__constant__ unsigned char c_light[24][2] = {
    {0,0},{1,0},{2,0},{0,1},{3,0},{1,1},{4,0},{2,1},{0,2},{5,0},{3,1},{1,2},
    {2,7},{4,6},{6,5},{3,7},{5,6},{7,5},{4,7},{6,6},{5,7},{7,6},{6,7},{7,7}
};

// Kernel 1: EXACT round-2 prefix body (best measured draws: 2.62us / 2.50us).
// 32 blocks x 256; blk = b*16 + c*4 + eq (eq = 16-wide e slice).
__global__ void __launch_bounds__(256) k_chunk_prefix(const float* __restrict__ Q,
                                                      const float* __restrict__ V) {
    int blk = blockIdx.x;
    int b  = blk >> 4;
    int c  = (blk >> 2) & 3;
    int eq = blk & 3;

    __shared__ float Wsm[64][16];

    int tid = threadIdx.x;
    int ul  = tid >> 2;   // 0..63
    int e4  = tid & 3;    // float4 column within the 16-e slice

    const float4* Q4 = reinterpret_cast<const float4*>(Q) + b * (PER_B / 4);
    const float4* V4 = reinterpret_cast<const float4*>(V) + b * (PER_B / 4);

    int u = c * 64 + ul;
    int base4 = u * 128 + eq * 4 + e4;   // float4 index of (u*512 + eq*16 + e4*4)

    float4 acc = make_float4(0.f, 0.f, 0.f, 0.f);
    #pragma unroll
    for (int r = 0; r < 8; r++) {
        float4 q = Q4[base4 + r * 16];
        float4 v = V4[base4 + r * 16];
        acc.x = fmaf(q.x, v.x, acc.x);
        acc.y = fmaf(q.y, v.y, acc.y);
        acc.z = fmaf(q.z, v.z, acc.z);
        acc.w = fmaf(q.w, v.w, acc.w);
    }
    *reinterpret_cast<float4*>(&Wsm[ul][e4 * 4]) = acc;
    __syncthreads();

    // Serial inclusive prefix along u for the 16 e-columns of this slice.
    if (tid < 16) {
        float a = 0.f;
        #pragma unroll
        for (int i = 0; i < 64; i++) {
            a += Wsm[i][tid];
            g_CP[b][c][i][eq * 16 + tid] = a;
        }
    }
}

// Kernel 2: EXACT round-15 stage2 (best measured draw: 4.96us, all 4096 rows).
// 96 blocks x 512 threads.
//   Blocks 0..79  : heavy rows — one per half-warp, lane covers e = 4l..4l+3.
//   Blocks 80..95 : uniform rows (no CP dependency) under the heavy umbrella.
__global__ void __launch_bounds__(512) k_stage2(const float* __restrict__ V,
                                                float* __restrict__ out) {
    int tid = threadIdx.x;
    int blk = blockIdx.x;

    const float4* V4g  = reinterpret_cast<const float4*>(V);
    float4*       out4 = reinterpret_cast<float4*>(out);

    if (blk >= 80) {
        // ---- Uniform rows: 24576 float4-slot tasks / 8192 workers = 3 passes ----
        const float uinv = 1.0f / 64.0f;
        int k0 = (blk - 80) * 512 + tid;
        #pragma unroll
        for (int it = 0; it < 3; it++) {
            int k = k0 + it * 8192;
            int r = k >> 4, l = k & 15;
            int bb = r >= 768;
            int rr = r - bb * 768;
            int pi = rr >> 5, s_hi = rr & 31;
            int h  = c_light[pi][0], s7 = c_light[pi][1];
            int grow = ((bb * 8 + h) << 8) + s_hi * 8 + s7;
            float4 vv = V4g[grow * 16 + l];
            out4[(OUT_HALF / 4) + grow * 16 + l] =
                make_float4(uinv, uinv, uinv, uinv);
            out4[grow * 16 + l] =
                make_float4(vv.x * uinv, vv.y * uinv, vv.z * uinv, vv.w * uinv);
        }
        return;
    }

    // ---- Heavy rows: 2560 rows, one per half-warp ----
    int hw = tid >> 4;          // half-warp id within block: 0..31
    int l  = tid & 15;          // e-slot

    int rowid = blk * 32 + hw;             // 0..2559
    int b     = rowid >= 1280;
    int rem   = rowid - b * 1280;
    int vi    = rem >> 7;                  // 0..9
    int rem2  = rem & 127;
    int combo = rem2 >> 5;                 // 0..3
    int s_hi  = rem2 & 31;
    int v  = vi + 6;
    int s7 = ((v - 6) >> 1) + combo;
    int h  = v - 2 * s7;
    int grow = ((b * 8 + h) << 8) + s_hi * 8 + s7;
    int base = (((v << 5) + 256) & 511) + s_hi;   // base_row, <= 511

    // Early V load (pure input).
    int off4 = grow * 16 + l;
    float4 vv = V4g[off4];

    const float4* CP4 = reinterpret_cast<const float4*>(g_CP);
    float4 sc = make_float4(0.f, 0.f, 0.f, 0.f);

    if (base < 256) {
        int lo = base, hi = min(base + 63, 255);
        int c0 = lo >> 6, c1 = hi >> 6;
        int i0 = lo & 63, i1 = hi & 63;
        float4 hiV = CP4[((b * 4 + c1) * 64 + i1) * 16 + l];
        float4 loV = make_float4(0.f, 0.f, 0.f, 0.f);
        if (i0 > 0) loV = CP4[((b * 4 + c0) * 64 + (i0 - 1)) * 16 + l];
        if (c0 == c1) {
            sc = make_float4(hiV.x - loV.x, hiV.y - loV.y,
                             hiV.z - loV.z, hiV.w - loV.w);
        } else {
            float4 T = CP4[((b * 4 + c0) * 64 + 63) * 16 + l];
            sc = make_float4((T.x - loV.x) + hiV.x, (T.y - loV.y) + hiV.y,
                             (T.z - loV.z) + hiV.z, (T.w - loV.w) + hiV.w);
        }
    } else if (base > 448) {
        sc = CP4[((b * 4 + 0) * 64 + (base - 449)) * 16 + l];  // wrap: chunk 0
    }
    // else (v=6, s_hi=0): empty -> sc = 0 -> uniform softmax

    // softmax over 64 e's: 4 per lane, reduce across the 16-lane half-warp.
    float m = fmaxf(fmaxf(sc.x, sc.y), fmaxf(sc.z, sc.w));
    #pragma unroll
    for (int d_ = 8; d_ > 0; d_ >>= 1)
        m = fmaxf(m, __shfl_xor_sync(0xffffffffu, m, d_));

    float e0 = __expf(sc.x - m);
    float e1 = __expf(sc.y - m);
    float e2 = __expf(sc.z - m);
    float e3 = __expf(sc.w - m);
    float ssum = (e0 + e1) + (e2 + e3);
    #pragma unroll
    for (int d_ = 8; d_ > 0; d_ >>= 1)
        ssum += __shfl_xor_sync(0xffffffffu, ssum, d_);
    float inv = __frcp_rn(ssum);

    float4 a = make_float4(e0 * inv, e1 * inv, e2 * inv, e3 * inv);

    out4[(OUT_HALF / 4) + off4] = a;                                       // attn
    out4[off4] = make_float4(a.x * vv.x, a.y * vv.y, a.z * vv.z, a.w * vv.w); // context
}

extern "C" void kernel_launch(void* const* d_in, const int* in_sizes, int n_in,
                              void* d_out, int out_size) {
    const float* Q = (const float*)d_in[0];
    // d_in[1] (K) is genuinely unused by the reference computation.
    const float* V = (const float*)d_in[2];
    float* out = (float*)d_out;

    k_chunk_prefix<<<32, 256>>>(Q, V);
    k_stage2<<<96, 512>>>(V, out);
}